// round 12
// baseline (speedup 1.0000x reference)
#include <cuda_runtime.h>
#include <cuda_fp16.h>
#include <math.h>
#include <stdint.h>

#define NROWS 16384
#define MROWS 16384
#define DDIM  512

// ---------------- scratch (no cudaMalloc allowed) ----------------
__device__ __align__(16) __half g_xh[NROWS * DDIM];   // fp16(x)
__device__ __align__(16) __half g_yh[MROWS * DDIM];   // fp16 hi of y
__device__ __align__(16) __half g_yl[MROWS * DDIM];   // fp16 lo of y
__device__ float        g_xsq[NROWS];
__device__ float        g_ysq[MROWS];
__device__ unsigned int g_min[NROWS];

__device__ __forceinline__ uint32_t smem_u32(const void* p) {
    uint32_t a;
    asm("{ .reg .u64 t; cvta.to.shared.u64 t, %1; cvt.u32.u64 %0, t; }"
        : "=r"(a) : "l"(p));
    return a;
}

// ---------------- GEMM config ----------------
#define BK          32                   // fp16 k per chunk = 64 B rows (swizzled)
#define NCHUNK      (DDIM / BK)          // 16
#define ROWB        64
#define TILEB       (128 * ROWB)         // 8192
#define STAGEB      (3 * TILEB)          // 24576 (X, Yh, Yl)
#define STAGES      4
#define SM_DATA0    1024
#define SM_TOTAL    (SM_DATA0 + STAGES * STAGEB)   // 99328 -> 2 CTAs/SM

// 16B-chunk XOR swizzle on 64B rows (conflict-free for cp.async + ldsm)
#define SWZ64(row, col) ((uint32_t)(row) * 64u + \
    ((((uint32_t)(col) >> 4) ^ (((uint32_t)(row) >> 1) & 3u)) << 4) + ((uint32_t)(col) & 15u))

// ---------------------------------------------------------------------------
// Kernel 1: fp16 conversion (x single, y hi/lo split) + exact norms + init
// ---------------------------------------------------------------------------
__global__ void kc_prep_kernel(const float* __restrict__ x,
                               const float* __restrict__ y) {
    int row = blockIdx.x;
    int tid = threadIdx.x;   // 128 threads * 4 elems = 512
    float4 a = ((const float4*)(x + (size_t)row * DDIM))[tid];
    float4 b = ((const float4*)(y + (size_t)row * DDIM))[tid];

    float av[4] = {a.x, a.y, a.z, a.w};
    float bv[4] = {b.x, b.y, b.z, b.w};
    unsigned short xh[4], yh[4], yl[4];
    float sx = 0.f, sy = 0.f;
    #pragma unroll
    for (int i = 0; i < 4; i++) {
        xh[i] = __half_as_ushort(__float2half_rn(av[i]));
        sx += av[i] * av[i];
        __half h = __float2half_rn(bv[i]);
        yh[i] = __half_as_ushort(h);
        yl[i] = __half_as_ushort(__float2half_rn(bv[i] - __half2float(h)));
        sy += bv[i] * bv[i];
    }
    uint2 u;
    u.x = (uint32_t)xh[0] | ((uint32_t)xh[1] << 16); u.y = (uint32_t)xh[2] | ((uint32_t)xh[3] << 16);
    ((uint2*)(g_xh + (size_t)row * DDIM))[tid] = u;
    u.x = (uint32_t)yh[0] | ((uint32_t)yh[1] << 16); u.y = (uint32_t)yh[2] | ((uint32_t)yh[3] << 16);
    ((uint2*)(g_yh + (size_t)row * DDIM))[tid] = u;
    u.x = (uint32_t)yl[0] | ((uint32_t)yl[1] << 16); u.y = (uint32_t)yl[2] | ((uint32_t)yl[3] << 16);
    ((uint2*)(g_yl + (size_t)row * DDIM))[tid] = u;

    #pragma unroll
    for (int o = 16; o > 0; o >>= 1) {
        sx += __shfl_down_sync(0xffffffffu, sx, o);
        sy += __shfl_down_sync(0xffffffffu, sy, o);
    }
    __shared__ float shx[4], shy[4];
    if ((tid & 31) == 0) { shx[tid >> 5] = sx; shy[tid >> 5] = sy; }
    __syncthreads();
    if (tid == 0) g_xsq[row] = shx[0] + shx[1] + shx[2] + shx[3];
    if (tid == 1) g_ysq[row] = shy[0] + shy[1] + shy[2] + shy[3];
    if (tid == 2) g_min[row] = 0x7f800000u;
}

// ---------------------------------------------------------------------------
// cp.async tile loader: one 32-k chunk (3 planes x 128 rows x 64 B, swizzled)
// ---------------------------------------------------------------------------
__device__ __forceinline__ void issue_loads(uint32_t stage_smem, int c,
                                            int bm, int bn, int tid) {
    #pragma unroll
    for (int i = 0; i < 6; i++) {
        const int t = i >> 1;                     // plane id, compile-time
        const int sub = (i & 1) * 256 + tid;      // 0..511 (16B-chunk id in plane)
        const int row = sub >> 2;
        const int ch  = (sub & 3) * 16;
        const char* base = (t == 0) ? (const char*)g_xh :
                           (t == 1) ? (const char*)g_yh : (const char*)g_yl;
        const int grow = ((t == 0) ? bm : bn) + row;
        const char* src = base + (size_t)grow * (DDIM * 2) + c * (BK * 2) + ch;
        const uint32_t dst = stage_smem + t * TILEB + SWZ64(row, ch);
        asm volatile("cp.async.cg.shared.global [%0], [%1], 16;"
                     :: "r"(dst), "l"(src) : "memory");
    }
    asm volatile("cp.async.commit_group;" ::: "memory");
}

__device__ __forceinline__ void ldsm4(uint32_t* r, uint32_t addr) {
    asm volatile("ldmatrix.sync.aligned.m8n8.x4.shared.b16 {%0,%1,%2,%3}, [%4];"
                 : "=r"(r[0]), "=r"(r[1]), "=r"(r[2]), "=r"(r[3]) : "r"(addr));
}
__device__ __forceinline__ void mma16816(float* d, const uint32_t* a, const uint32_t* b) {
    asm volatile("mma.sync.aligned.m16n8k16.row.col.f32.f16.f16.f32 "
                 "{%0,%1,%2,%3}, {%4,%5,%6,%7}, {%8,%9}, {%0,%1,%2,%3};"
                 : "+f"(d[0]), "+f"(d[1]), "+f"(d[2]), "+f"(d[3])
                 : "r"(a[0]), "r"(a[1]), "r"(a[2]), "r"(a[3]), "r"(b[0]), "r"(b[1]));
}

// ---------------------------------------------------------------------------
// Kernel 2: asymmetric fp16 GEMM (dot = x*yhi + x*ylo), fused row-min
// 128x128 CTA, 8 warps (2M x 4N), warp 64x32, 4-stage + 2 CTAs/SM
// ---------------------------------------------------------------------------
__global__ void __launch_bounds__(256, 2)
kc_gemm_kernel() {
    extern __shared__ char smem[];
    float*        sy     = (float*)smem;                 // [128]
    unsigned int* rowmin = (unsigned int*)(smem + 512);  // [128]
    const uint32_t sdata = smem_u32(smem) + SM_DATA0;

    const int tid  = threadIdx.x;
    const int wid  = tid >> 5;
    const int lane = tid & 31;
    const int bm = blockIdx.y * 128;
    const int bn = blockIdx.x * 128;
    const int warp_m = (wid >> 2) * 64;   // 0 or 64
    const int warp_n = (wid & 3) * 32;    // 0,32,64,96

    if (tid < 128) sy[tid] = g_ysq[bn + tid];
    else           rowmin[tid - 128] = 0x7f800000u;

    // per-lane ldmatrix row/col components
    const int arow = ((lane >> 3) & 1) * 8 + (lane & 7);
    const int acol = (lane >> 4) * 16;
    const int brow = (lane >> 4) * 8 + (lane & 7);
    const int bcol = ((lane >> 3) & 1) * 16;

    uint32_t aoff[2][4], boff[2][2];
    #pragma unroll
    for (int kk = 0; kk < 2; kk++) {
        const int colb = kk * 32;
        #pragma unroll
        for (int mt = 0; mt < 4; mt++)
            aoff[kk][mt] = SWZ64(warp_m + mt * 16 + arow, colb + acol);
        #pragma unroll
        for (int q = 0; q < 2; q++)
            boff[kk][q] = SWZ64(warp_n + q * 16 + brow, colb + bcol);
    }

    float acc[4][4][4];
    #pragma unroll
    for (int mt = 0; mt < 4; mt++)
        #pragma unroll
        for (int nt = 0; nt < 4; nt++)
            #pragma unroll
            for (int e = 0; e < 4; e++) acc[mt][nt][e] = 0.f;

    issue_loads(sdata + 0 * STAGEB, 0, bm, bn, tid);
    issue_loads(sdata + 1 * STAGEB, 1, bm, bn, tid);
    issue_loads(sdata + 2 * STAGEB, 2, bm, bn, tid);

    #pragma unroll 1
    for (int c = 0; c < NCHUNK; c++) {
        asm volatile("cp.async.wait_group 2;" ::: "memory");
        __syncthreads();   // chunk c visible; all warps done with chunk c-1

        if (c + 3 < NCHUNK)
            issue_loads(sdata + ((c + 3) & 3) * STAGEB, c + 3, bm, bn, tid);
        else
            asm volatile("cp.async.commit_group;" ::: "memory");

        const uint32_t st = sdata + (c & 3) * STAGEB;
        const uint32_t X  = st;
        const uint32_t Yh = st + TILEB;
        const uint32_t Yl = st + 2 * TILEB;

        // hoist ALL B fragments (both k16 halves, both planes)
        uint32_t bh[2][4][2], bl[2][4][2];
        #pragma unroll
        for (int kk = 0; kk < 2; kk++) {
            #pragma unroll
            for (int q = 0; q < 2; q++) {
                uint32_t r[4];
                ldsm4(r, Yh + boff[kk][q]);
                bh[kk][2*q][0] = r[0]; bh[kk][2*q][1] = r[1];
                bh[kk][2*q+1][0] = r[2]; bh[kk][2*q+1][1] = r[3];
                ldsm4(r, Yl + boff[kk][q]);
                bl[kk][2*q][0] = r[0]; bl[kk][2*q][1] = r[1];
                bl[kk][2*q+1][0] = r[2]; bl[kk][2*q+1][1] = r[3];
            }
        }
        #pragma unroll
        for (int kk = 0; kk < 2; kk++) {
            #pragma unroll
            for (int mt = 0; mt < 4; mt++) {
                uint32_t ax[4];
                ldsm4(ax, X + aoff[kk][mt]);
                #pragma unroll
                for (int nt = 0; nt < 4; nt++) {
                    mma16816(acc[mt][nt], ax, bh[kk][nt]);
                    mma16816(acc[mt][nt], ax, bl[kk][nt]);
                }
            }
        }
    }
    __syncthreads();

    // epilogue: fused squared-distance row-min
    #pragma unroll
    for (int mt = 0; mt < 4; mt++) {
        #pragma unroll
        for (int h = 0; h < 2; h++) {
            const int lrow = warp_m + mt * 16 + (lane >> 2) + h * 8;
            float mn = __int_as_float(0x7f800000);
            #pragma unroll
            for (int nt = 0; nt < 4; nt++) {
                #pragma unroll
                for (int e = 0; e < 2; e++) {
                    const int col = warp_n + nt * 8 + (lane & 3) * 2 + e;
                    mn = fminf(mn, fmaf(-2.0f, acc[mt][nt][h * 2 + e], sy[col]));
                }
            }
            mn = fminf(mn, __shfl_xor_sync(0xffffffffu, mn, 1));
            mn = fminf(mn, __shfl_xor_sync(0xffffffffu, mn, 2));
            if ((lane & 3) == 0) {
                float s = fmaxf(g_xsq[bm + lrow] + mn, 0.0f);
                atomicMin(&rowmin[lrow], __float_as_uint(s));
            }
        }
    }
    __syncthreads();
    if (tid < 128) atomicMin(&g_min[bm + tid], rowmin[tid]);
}

// ---------------------------------------------------------------------------
// Kernel 3: argmax over min squared distances (tie-break lowest index)
// ---------------------------------------------------------------------------
__global__ void kc_argmax_kernel(float* __restrict__ out) {
    const int tid = threadIdx.x;  // 1024
    unsigned long long best = 0ull;
    for (int i = tid; i < NROWS; i += 1024) {
        unsigned long long key = ((unsigned long long)g_min[i] << 32) |
                                 (unsigned long long)(0xffffffffu - (unsigned)i);
        if (key > best) best = key;
    }
    #pragma unroll
    for (int o = 16; o > 0; o >>= 1) {
        unsigned long long v = __shfl_down_sync(0xffffffffu, best, o);
        if (v > best) best = v;
    }
    __shared__ unsigned long long sh[32];
    if ((tid & 31) == 0) sh[tid >> 5] = best;
    __syncthreads();
    if (tid < 32) {
        best = sh[tid];
        #pragma unroll
        for (int o = 16; o > 0; o >>= 1) {
            unsigned long long v = __shfl_down_sync(0xffffffffu, best, o);
            if (v > best) best = v;
        }
        if (tid == 0) {
            unsigned int vbits = (unsigned int)(best >> 32);
            int idx = (int)(0xffffffffu - (unsigned int)(best & 0xffffffffu));
            out[0] = sqrtf(__uint_as_float(vbits));
            out[1] = (float)idx;
        }
    }
}

// ---------------------------------------------------------------------------
extern "C" void kernel_launch(void* const* d_in, const int* in_sizes, int n_in,
                              void* d_out, int out_size) {
    const float* x = (const float*)d_in[0];
    const float* y = (const float*)d_in[1];
    float* out = (float*)d_out;

    cudaFuncSetAttribute(kc_gemm_kernel,
                         cudaFuncAttributeMaxDynamicSharedMemorySize, SM_TOTAL);

    kc_prep_kernel<<<NROWS, 128>>>(x, y);

    dim3 grid(MROWS / 128, NROWS / 128);
    kc_gemm_kernel<<<grid, 256, SM_TOTAL>>>();

    kc_argmax_kernel<<<1, 1024>>>(out);
}

// round 17
// speedup vs baseline: 1.4777x; 1.4777x over previous
#include <cuda_runtime.h>
#include <math.h>
#include <stdint.h>

#define NROWS 16384
#define MROWS 16384
#define DDIM  512

// ---------------- scratch (no cudaMalloc allowed) ----------------
// fragment-major packed tf32 operands (stored as fp32 bit patterns)
__device__ __align__(16) float g_xp[NROWS * DDIM];   // [rb128][kc16][mtile8][kstep4][lane32][4]
__device__ __align__(16) float g_yp[MROWS * DDIM];   // [cb128][kc16][ntile16][kpair2][lane32][4]
__device__ float        g_xsq[NROWS];
__device__ float        g_ysq[MROWS];
__device__ unsigned int g_min[NROWS];

__device__ __forceinline__ uint32_t smem_u32(const void* p) {
    uint32_t a;
    asm("{ .reg .u64 t; cvta.to.shared.u64 t, %1; cvt.u32.u64 %0, t; }"
        : "=r"(a) : "l"(p));
    return a;
}
__device__ __forceinline__ float tf32r(float f) {
    uint32_t u;
    asm("cvt.rna.tf32.f32 %0, %1;" : "=r"(u) : "f"(f));
    return __uint_as_float(u);
}

// ---------------- GEMM config ----------------
#define BK       32                      // k per chunk (4 k8-steps)
#define NCHUNK   (DDIM / BK)             // 16
#define APLANEB  16384                   // 8 mtiles * 4 ksteps * 512 B
#define BPLANEB  16384                   // 16 ntiles * 2 kpairs * 512 B
#define STAGEB   (APLANEB + BPLANEB)     // 32768
#define STAGES   3
#define SM_DATA0 1024
#define SM_TOTAL (SM_DATA0 + STAGES * STAGEB)   // 99328 -> 2 CTAs/SM

// ---------------------------------------------------------------------------
// Prep X: 16 rows/block -> fragment-major pack + exact norms + init g_min
// A-frag (m16n8k8): a0=[r=l/4][c=l%4] a1=[r+8][c] a2=[r][c+4] a3=[r+8][c+4]
// ---------------------------------------------------------------------------
__global__ void kc_prep_x(const float* __restrict__ x) {
    __shared__ float tile[16 * 512];
    const int tid  = threadIdx.x;          // 256
    const int row0 = blockIdx.x * 16;
    const int rb   = blockIdx.x >> 3;      // 128-row block
    const int mt   = blockIdx.x & 7;       // mtile within block

    #pragma unroll
    for (int i = 0; i < 8; i++) {
        int idx = tid + i * 256;           // float4 id, 0..2047
        int r = idx >> 7, c4 = idx & 127;
        float4 v = ((const float4*)(x + (size_t)(row0 + r) * DDIM))[c4];
        ((float4*)tile)[idx] = v;
    }
    __syncthreads();

    // norms: row = tid>>4, segment = tid&15 (32 elems each)
    {
        int r = tid >> 4, seg = tid & 15;
        const float* tr = tile + r * 512 + seg * 32;
        float s = 0.f;
        #pragma unroll
        for (int j = 0; j < 32; j++) s += tr[j] * tr[j];
        #pragma unroll
        for (int o = 8; o > 0; o >>= 1) s += __shfl_down_sync(0xffffffffu, s, o, 16);
        if (seg == 0) g_xsq[row0 + r] = s;
    }
    if (tid < 16) g_min[row0 + tid] = 0x7f800000u;

    // pack: 2048 lane-quads, 8 per thread
    #pragma unroll
    for (int i = 0; i < 8; i++) {
        int q    = tid + i * 256;          // 0..2047
        int kc   = q >> 7;                 // 0..15
        int rem  = q & 127;
        int ks   = rem >> 5;               // 0..3
        int lane = rem & 31;
        int lr = lane >> 2, lc = lane & 3;
        int colb = kc * 32 + ks * 8;
        float4 o;
        o.x = tf32r(tile[lr * 512 + colb + lc]);
        o.y = tf32r(tile[(lr + 8) * 512 + colb + lc]);
        o.z = tf32r(tile[lr * 512 + colb + lc + 4]);
        o.w = tf32r(tile[(lr + 8) * 512 + colb + lc + 4]);
        size_t fidx = ((((size_t)rb * 16 + kc) * 8 + mt) * 4 + ks) * 128 + lane * 4;
        *(float4*)(g_xp + fidx) = o;
    }
}

// ---------------------------------------------------------------------------
// Prep Y: 8 rows/block -> fragment-major pack + exact norms
// B-frag (k8xn8, col): b0=[k=l%4][n=l/4] b1=[k+4][n]; packed kpairs of 2 ksteps
// ---------------------------------------------------------------------------
__global__ void kc_prep_y(const float* __restrict__ y) {
    __shared__ float tile[8 * 512];
    const int tid  = threadIdx.x;          // 256
    const int row0 = blockIdx.x * 8;
    const int cb   = blockIdx.x >> 4;      // 128-col block
    const int nt   = blockIdx.x & 15;      // ntile within block

    #pragma unroll
    for (int i = 0; i < 4; i++) {
        int idx = tid + i * 256;           // float4 id, 0..1023
        int r = idx >> 7, c4 = idx & 127;
        float4 v = ((const float4*)(y + (size_t)(row0 + r) * DDIM))[c4];
        ((float4*)tile)[idx] = v;
    }
    __syncthreads();

    // norms: warp w = row, lane sums 16 elems
    {
        int r = tid >> 5, lane = tid & 31;
        const float* tr = tile + r * 512 + lane * 16;
        float s = 0.f;
        #pragma unroll
        for (int j = 0; j < 16; j++) s += tr[j] * tr[j];
        #pragma unroll
        for (int o = 16; o > 0; o >>= 1) s += __shfl_down_sync(0xffffffffu, s, o);
        if (lane == 0) g_ysq[row0 + r] = s;
    }

    // pack: 1024 lane-quads, 4 per thread
    #pragma unroll
    for (int i = 0; i < 4; i++) {
        int q    = tid + i * 256;          // 0..1023
        int kc   = q >> 6;                 // 0..15
        int rem  = q & 63;
        int p    = rem >> 5;               // kpair 0..1
        int lane = rem & 31;
        int ln = lane >> 2, lk = lane & 3;
        int c0 = kc * 32 + (2 * p) * 8;
        int c1 = kc * 32 + (2 * p + 1) * 8;
        float4 o;
        o.x = tf32r(tile[ln * 512 + c0 + lk]);
        o.y = tf32r(tile[ln * 512 + c0 + lk + 4]);
        o.z = tf32r(tile[ln * 512 + c1 + lk]);
        o.w = tf32r(tile[ln * 512 + c1 + lk + 4]);
        size_t fidx = ((((size_t)cb * 16 + kc) * 16 + nt) * 2 + p) * 128 + lane * 4;
        *(float4*)(g_yp + fidx) = o;
    }
}

// ---------------------------------------------------------------------------
// cp.async loader: fully linear 32 KB stage (A 16KB | B 16KB)
// ---------------------------------------------------------------------------
__device__ __forceinline__ void issue_loads(uint32_t stage_smem, int c,
                                            int bm, int bn, int tid) {
    const char* asrc = (const char*)(g_xp + ((size_t)(bm >> 7) * 16 + c) * 4096);
    const char* bsrc = (const char*)(g_yp + ((size_t)(bn >> 7) * 16 + c) * 4096);
    #pragma unroll
    for (int i = 0; i < 4; i++) {
        const uint32_t o = (tid + i * 256) * 16;
        asm volatile("cp.async.cg.shared.global [%0], [%1], 16;"
                     :: "r"(stage_smem + o), "l"(asrc + o) : "memory");
    }
    #pragma unroll
    for (int i = 0; i < 4; i++) {
        const uint32_t o = (tid + i * 256) * 16;
        asm volatile("cp.async.cg.shared.global [%0], [%1], 16;"
                     :: "r"(stage_smem + APLANEB + o), "l"(bsrc + o) : "memory");
    }
    asm volatile("cp.async.commit_group;" ::: "memory");
}

__device__ __forceinline__ void mma_tf32(float* d, const uint32_t* a, const uint32_t* b) {
    asm volatile("mma.sync.aligned.m16n8k8.row.col.f32.tf32.tf32.f32 "
                 "{%0,%1,%2,%3}, {%4,%5,%6,%7}, {%8,%9}, {%0,%1,%2,%3};"
                 : "+f"(d[0]), "+f"(d[1]), "+f"(d[2]), "+f"(d[3])
                 : "r"(a[0]), "r"(a[1]), "r"(a[2]), "r"(a[3]), "r"(b[0]), "r"(b[1]));
}

// ---------------------------------------------------------------------------
// Kernel 2: tf32 1-term GEMM, fused row-min
// 128x128 CTA, 8 warps (2M x 4N), warp 64x32, 3-stage + 2 CTAs/SM
// ---------------------------------------------------------------------------
__global__ void __launch_bounds__(256, 2)
kc_gemm_kernel() {
    extern __shared__ char smem[];
    float*        syn    = (float*)smem;                 // [128]
    unsigned int* rowmin = (unsigned int*)(smem + 512);  // [128]
    char* sdata = smem + SM_DATA0;

    const int tid  = threadIdx.x;
    const int wid  = tid >> 5;
    const int lane = tid & 31;
    const int bm = blockIdx.y * 128;
    const int bn = blockIdx.x * 128;
    const int warp_m = (wid >> 2) * 64;   // 0 or 64
    const int warp_n = (wid & 3) * 32;    // 0,32,64,96
    const uint32_t sdata_u = smem_u32(sdata);

    if (tid < 128) syn[tid] = g_ysq[bn + tid];
    else           rowmin[tid - 128] = 0x7f800000u;

    // loop-invariant fragment base offsets within a stage
    const uint32_t abase = (uint32_t)(warp_m >> 4) * 4 * 512 + lane * 16;
    const uint32_t bbase = APLANEB + (uint32_t)(warp_n >> 3) * 2 * 512 + lane * 16;

    float acc[4][4][4];
    #pragma unroll
    for (int mt = 0; mt < 4; mt++)
        #pragma unroll
        for (int nt = 0; nt < 4; nt++)
            #pragma unroll
            for (int e = 0; e < 4; e++) acc[mt][nt][e] = 0.f;

    issue_loads(sdata_u + 0 * STAGEB, 0, bm, bn, tid);
    issue_loads(sdata_u + 1 * STAGEB, 1, bm, bn, tid);

    int stage = 0, nstage = 2;
    #pragma unroll 1
    for (int c = 0; c < NCHUNK; c++) {
        asm volatile("cp.async.wait_group 1;" ::: "memory");
        __syncthreads();   // chunk c visible; all warps done with chunk c-1

        if (c + 2 < NCHUNK)
            issue_loads(sdata_u + nstage * STAGEB, c + 2, bm, bn, tid);
        else
            asm volatile("cp.async.commit_group;" ::: "memory");

        const char* st = sdata + stage * STAGEB;

        #pragma unroll
        for (int p = 0; p < 2; p++) {          // kpairs (2 k8-steps each)
            uint32_t bf[4][4];
            #pragma unroll
            for (int nt = 0; nt < 4; nt++) {
                uint4 v = *(const uint4*)(st + bbase + (uint32_t)(nt * 2 + p) * 512);
                bf[nt][0] = v.x; bf[nt][1] = v.y; bf[nt][2] = v.z; bf[nt][3] = v.w;
            }
            #pragma unroll
            for (int s = 0; s < 2; s++) {      // kstep within pair
                const int ks = 2 * p + s;
                #pragma unroll
                for (int mt = 0; mt < 4; mt++) {
                    uint4 av = *(const uint4*)(st + abase + (uint32_t)(mt * 4 + ks) * 512);
                    uint32_t a[4] = {av.x, av.y, av.z, av.w};
                    #pragma unroll
                    for (int nt = 0; nt < 4; nt++)
                        mma_tf32(acc[mt][nt], a, &bf[nt][2 * s]);
                }
            }
        }
        stage = (stage == STAGES - 1) ? 0 : stage + 1;
        nstage = (nstage == STAGES - 1) ? 0 : nstage + 1;
    }
    __syncthreads();

    // epilogue: fused squared-distance row-min (m16n8 D layout)
    #pragma unroll
    for (int mt = 0; mt < 4; mt++) {
        #pragma unroll
        for (int h = 0; h < 2; h++) {
            const int lrow = warp_m + mt * 16 + (lane >> 2) + h * 8;
            float mn = __int_as_float(0x7f800000);
            #pragma unroll
            for (int nt = 0; nt < 4; nt++) {
                #pragma unroll
                for (int e = 0; e < 2; e++) {
                    const int col = warp_n + nt * 8 + (lane & 3) * 2 + e;
                    mn = fminf(mn, fmaf(-2.0f, acc[mt][nt][h * 2 + e], syn[col]));
                }
            }
            mn = fminf(mn, __shfl_xor_sync(0xffffffffu, mn, 1));
            mn = fminf(mn, __shfl_xor_sync(0xffffffffu, mn, 2));
            if ((lane & 3) == 0) {
                float s = fmaxf(g_xsq[bm + lrow] + mn, 0.0f);
                atomicMin(&rowmin[lrow], __float_as_uint(s));
            }
        }
    }
    __syncthreads();
    if (tid < 128) atomicMin(&g_min[bm + tid], rowmin[tid]);
}

// ---------------------------------------------------------------------------
// Kernel 3: argmax over min squared distances (tie-break lowest index)
// ---------------------------------------------------------------------------
__global__ void kc_argmax_kernel(float* __restrict__ out) {
    const int tid = threadIdx.x;  // 1024
    unsigned long long best = 0ull;
    for (int i = tid; i < NROWS; i += 1024) {
        unsigned long long key = ((unsigned long long)g_min[i] << 32) |
                                 (unsigned long long)(0xffffffffu - (unsigned)i);
        if (key > best) best = key;
    }
    #pragma unroll
    for (int o = 16; o > 0; o >>= 1) {
        unsigned long long v = __shfl_down_sync(0xffffffffu, best, o);
        if (v > best) best = v;
    }
    __shared__ unsigned long long sh[32];
    if ((tid & 31) == 0) sh[tid >> 5] = best;
    __syncthreads();
    if (tid < 32) {
        best = sh[tid];
        #pragma unroll
        for (int o = 16; o > 0; o >>= 1) {
            unsigned long long v = __shfl_down_sync(0xffffffffu, best, o);
            if (v > best) best = v;
        }
        if (tid == 0) {
            unsigned int vbits = (unsigned int)(best >> 32);
            int idx = (int)(0xffffffffu - (unsigned int)(best & 0xffffffffu));
            out[0] = sqrtf(__uint_as_float(vbits));
            out[1] = (float)idx;
        }
    }
}

// ---------------------------------------------------------------------------
extern "C" void kernel_launch(void* const* d_in, const int* in_sizes, int n_in,
                              void* d_out, int out_size) {
    const float* x = (const float*)d_in[0];
    const float* y = (const float*)d_in[1];
    float* out = (float*)d_out;

    cudaFuncSetAttribute(kc_gemm_kernel,
                         cudaFuncAttributeMaxDynamicSharedMemorySize, SM_TOTAL);

    kc_prep_x<<<NROWS / 16, 256>>>(x);
    kc_prep_y<<<MROWS / 8, 256>>>(y);

    dim3 grid(MROWS / 128, NROWS / 128);
    kc_gemm_kernel<<<grid, 256, SM_TOTAL>>>();

    kc_argmax_kernel<<<1, 1024>>>(out);
}